// round 9
// baseline (speedup 1.0000x reference)
#include <cuda_runtime.h>
#include <cuda_fp16.h>
#include <cstdint>
#include <math.h>

// ConvergedInhibition == circular deconvolution along C=128 channels.
// Y = G @ X, G[r][j] = g[(r-j)&127], g = ifft(1/fft(delta-k)).
// R9: R8 pipeline with the k-loop FIXED (8 ksteps, one per j-block).
//     Persistent CTAs (2/SM), double-buffered: LDG batch j for tile t+1
//     issued before kstep j of tile t's mma; convert+STS after.
//     Single-pass fp16 mma, register A-frags (circulant diagonal classes),
//     permuted-column coalesced STG.128 epilogue.

#define CCH     128
#define HWSZ    4096
#define NBATCH  64
#define SCOPE   27
#define NTILE   128
#define NTHREADS 256
#define NTILES_TOTAL (NBATCH * (HWSZ / NTILE))   // 2048

#define XPITCH_B 272                       // bytes per n-row (17*16B)
#define BUF_B    (NTILE * XPITCH_B)        // 34816
#define SMEM_DYN (2 * BUF_B)               // 69632

__device__ uint4 a_frag8[8 * 32];          // [class][lane], fp16 G frags

// ---------------------------------------------------------------------------
__device__ __forceinline__ uint32_t s2u(const void* p) {
    uint32_t a;
    asm("{ .reg .u64 t; cvta.to.shared.u64 t, %1; cvt.u32.u64 %0, t; }"
        : "=r"(a) : "l"(p));
    return a;
}
__device__ __forceinline__ uint32_t pack_f16x2(float lo, float hi) {
    uint32_t r;
    asm("cvt.rn.f16x2.f32 %0, %1, %2;" : "=r"(r) : "f"(hi), "f"(lo));
    return r;
}
__device__ __forceinline__ void ldsm_x4(uint32_t& r0, uint32_t& r1,
                                        uint32_t& r2, uint32_t& r3, uint32_t a) {
    asm volatile("ldmatrix.sync.aligned.m8n8.x4.shared.b16 {%0,%1,%2,%3}, [%4];"
                 : "=r"(r0), "=r"(r1), "=r"(r2), "=r"(r3) : "r"(a));
}
__device__ __forceinline__ void mma16816(float* c, const uint4& a,
                                         uint32_t b0, uint32_t b1) {
    asm volatile(
        "mma.sync.aligned.m16n8k16.row.col.f32.f16.f16.f32 "
        "{%0,%1,%2,%3}, {%4,%5,%6,%7}, {%8,%9}, {%0,%1,%2,%3};"
        : "+f"(c[0]), "+f"(c[1]), "+f"(c[2]), "+f"(c[3])
        : "r"(a.x), "r"(a.y), "r"(a.z), "r"(a.w), "r"(b0), "r"(b1));
}

// ---------------------------------------------------------------------------
// Prep: compute g (validated R1), write the 8-class A-fragment table.
// ---------------------------------------------------------------------------
__global__ void prep_kernel(const float* __restrict__ filt) {
    __shared__ float tw_re[CCH], tw_im[CCH];
    __shared__ float inv_re[CCH], inv_im[CCH];
    __shared__ float ft[SCOPE];
    __shared__ float g_s[CCH];
    int t = threadIdx.x;   // 0..255
    if (t < SCOPE) ft[t] = filt[t];
    if (t < CCH) {
        float s, c;
        sincosf(6.283185307179586f * (float)t / 128.0f, &s, &c);
        tw_re[t] = c; tw_im[t] = s;
    }
    __syncthreads();
    if (t < CCH) {
        float fr = 1.0f, fi = 0.0f;
#pragma unroll
        for (int j = 0; j < SCOPE; j++) {
            int p = (115 + j) & 127;
            int idx = (t * p) & 127;
            fr -= ft[j] * tw_re[idx];
            fi += ft[j] * tw_im[idx];
        }
        float d = fr * fr + fi * fi;
        inv_re[t] = fr / d; inv_im[t] = -fi / d;
    }
    __syncthreads();
    if (t < CCH) {
        float acc = 0.0f;
        for (int f = 0; f < CCH; f++) {
            int idx = (f * t) & 127;
            acc += tw_re[idx] * inv_re[f] - tw_im[idx] * inv_im[f];
        }
        g_s[t] = acc * (1.0f / 128.0f);
    }
    __syncthreads();

    {
        int cls  = t >> 5;          // 0..7
        int lane = t & 31;
        int d0 = (16 * cls + (lane >> 2) - 2 * (lane & 3)) & 127;
        uint4 h;
        h.x = pack_f16x2(g_s[d0], g_s[(d0 - 1) & 127]);
        int d1 = (d0 + 8) & 127;
        h.y = pack_f16x2(g_s[d1], g_s[(d1 - 1) & 127]);
        int d2 = (d0 - 8) & 127;
        h.z = pack_f16x2(g_s[d2], g_s[(d2 - 1) & 127]);
        h.w = h.x;
        a_frag8[t] = h;
    }
}

// ---------------------------------------------------------------------------
// per-j-block load / convert+store helpers (permuted columns, R6/R7 layout)
// ---------------------------------------------------------------------------
__device__ __forceinline__ void issue_loads(const float* pbase, int oct,
                                            float v[8]) {
    const float* p = pbase + (size_t)(oct * 8) * HWSZ;
#pragma unroll
    for (int i = 0; i < 8; i++) v[i] = __ldg(p + (size_t)i * HWSZ);
}
__device__ __forceinline__ void convert_store(char* dst, int oct,
                                              const float v[8]) {
    uint4 hq;
    hq.x = pack_f16x2(v[0], v[1]);
    hq.y = pack_f16x2(v[2], v[3]);
    hq.z = pack_f16x2(v[4], v[5]);
    hq.w = pack_f16x2(v[6], v[7]);
    *reinterpret_cast<uint4*>(dst + oct * 16) = hq;
}

// ---------------------------------------------------------------------------
// Persistent pipelined GEMM. Tile = 128 out-channels x 128 spatial cols.
// ---------------------------------------------------------------------------
__global__ void __launch_bounds__(NTHREADS, 2)
gemm_mma(const float* __restrict__ x, float* __restrict__ y) {
    extern __shared__ char smc[];
    const int tid  = threadIdx.x;
    const int wid  = tid >> 5;
    const int lane = tid & 31;
    const int warp_m = wid & 1;
    const int warp_n = wid >> 1;

    // A fragments for all (mt,ks): 8 diagonal classes, warp_m folded in.
    uint4 areg[8];
#pragma unroll
    for (int i = 0; i < 8; i++)
        areg[i] = a_frag8[(((warp_m << 2) + i) & 7) * 32 + lane];

    // per-thread load-lane constants (permuted column nu within 32-block)
    const int n0 = tid & 127;
    const int rr = n0 & 31;
    const int nu = ((rr & 6) << 2) | ((rr >> 2) & 6) | (rr & 1);
    const int col_ld = (n0 & ~31) + nu;     // column within tile, for loads
    const int oct0 = tid >> 7;              // 0 or 1
    const uint32_t dst_row_off = (uint32_t)n0 * XPITCH_B;

    const uint32_t smb = s2u(smc);
    const uint32_t lm_off = ((lane & 7) + ((lane >> 4) << 3)) * XPITCH_B
                          + ((lane >> 3) & 1) * 16
                          + (uint32_t)warp_n * 32 * XPITCH_B;

    int tile = blockIdx.x;
    if (tile >= NTILES_TOTAL) return;
    const int stride = gridDim.x;

    // ---- prologue: load tile into buf0 ----
    {
        const float* xb = x + (size_t)(tile >> 5) * CCH * HWSZ
                            + (tile & 31) * NTILE + col_ld;
        char* dst = smc + dst_row_off;
#pragma unroll
        for (int j = 0; j < 8; j++) {
            float v[8];
            issue_loads(xb, oct0 + 2 * j, v);
            convert_store(dst, oct0 + 2 * j, v);
        }
    }

    int cur = 0;
    for (; tile < NTILES_TOTAL; tile += stride) {
        const int nxt = tile + stride;
        const bool hn = nxt < NTILES_TOTAL;
        const float* xbn = hn
            ? x + (size_t)(nxt >> 5) * CCH * HWSZ + (nxt & 31) * NTILE + col_ld
            : (const float*)nullptr;
        char* dstn = smc + (cur ^ 1) * BUF_B + dst_row_off;

        __syncthreads();   // buf[cur] fully written; buf[cur^1] free

        float acc[4][4][4];
#pragma unroll
        for (int mt = 0; mt < 4; mt++)
#pragma unroll
            for (int nt = 0; nt < 4; nt++)
#pragma unroll
                for (int r = 0; r < 4; r++) acc[mt][nt][r] = 0.0f;

        const uint32_t xh_base = smb + (uint32_t)cur * BUF_B + lm_off;

        // 8 j-blocks == 8 ksteps (K=128, 16 k's per mma/ldsm step)
#pragma unroll
        for (int j = 0; j < 8; j++) {
            float v[8];
            if (hn) issue_loads(xbn, oct0 + 2 * j, v);
            const uint32_t kofs = (uint32_t)j * 32;
#pragma unroll
            for (int p = 0; p < 2; p++) {
                uint32_t b0, b1, b2, b3;
                ldsm_x4(b0, b1, b2, b3,
                        xh_base + p * (16 * XPITCH_B) + kofs);
#pragma unroll
                for (int mt = 0; mt < 4; mt++) {
                    const uint4& a = areg[(mt - j) & 7];
                    mma16816(acc[mt][2 * p],     a, b0, b1);
                    mma16816(acc[mt][2 * p + 1], a, b2, b3);
                }
            }
            if (hn) convert_store(dstn, oct0 + 2 * j, v);
        }

        // ---- epilogue: lane holds cols [8q,8q+8) of rows m0, m0+8 ----
        {
            float* yb = y + (size_t)(tile >> 5) * CCH * HWSZ
                          + (tile & 31) * NTILE;
            const int q = lane & 3;
#pragma unroll
            for (int mt = 0; mt < 4; mt++) {
                int m0 = warp_m * 64 + mt * 16 + (lane >> 2);
                float* yr0 = yb + (size_t)m0 * HWSZ + warp_n * 32 + 8 * q;
                float* yr8 = yr0 + (size_t)8 * HWSZ;
                *reinterpret_cast<float4*>(yr0) =
                    make_float4(acc[mt][0][0], acc[mt][0][1],
                                acc[mt][1][0], acc[mt][1][1]);
                *reinterpret_cast<float4*>(yr0 + 4) =
                    make_float4(acc[mt][2][0], acc[mt][2][1],
                                acc[mt][3][0], acc[mt][3][1]);
                *reinterpret_cast<float4*>(yr8) =
                    make_float4(acc[mt][0][2], acc[mt][0][3],
                                acc[mt][1][2], acc[mt][1][3]);
                *reinterpret_cast<float4*>(yr8 + 4) =
                    make_float4(acc[mt][2][2], acc[mt][2][3],
                                acc[mt][3][2], acc[mt][3][3]);
            }
        }
        cur ^= 1;
    }
}

// ---------------------------------------------------------------------------
extern "C" void kernel_launch(void* const* d_in, const int* in_sizes, int n_in,
                              void* d_out, int out_size) {
    const float* act  = (const float*)d_in[0];
    const float* filt = (const float*)d_in[1];
    if (n_in >= 2 && in_sizes[0] == SCOPE) {
        act  = (const float*)d_in[1];
        filt = (const float*)d_in[0];
    }
    float* out = (float*)d_out;

    prep_kernel<<<1, 256>>>(filt);

    int nsm = 148;
    cudaDeviceGetAttribute(&nsm, cudaDevAttrMultiProcessorCount, 0);
    int grid = 2 * nsm;
    if (grid > NTILES_TOTAL) grid = NTILES_TOTAL;

    cudaFuncSetAttribute(gemm_mma,
                         cudaFuncAttributeMaxDynamicSharedMemorySize, SMEM_DYN);
    gemm_mma<<<grid, NTHREADS, SMEM_DYN>>>(act, out);
}

// round 10
// speedup vs baseline: 1.3226x; 1.3226x over previous
#include <cuda_runtime.h>
#include <cuda_fp16.h>
#include <cstdint>
#include <math.h>

// ConvergedInhibition == circular deconvolution along C=128 channels.
// Y = G @ X, G[r][j] = g[(r-j)&127], g = ifft(1/fft(delta-k)).
// R10: persistent CTAs + cp.async staging: next tile's fp32 X is copied
//      gmem->smem by LDGSTS (no registers, full-tile latency cover), then
//      a short convert phase produces the fp16 [n][k] buffer (with the
//      epilogue column permutation). Single-pass fp16 mma, register A-frags
//      via circulant diagonal classes, coalesced STG.128 epilogue.
//      Tile = 128m x 64n. 2 CTAs/SM.

#define CCH     128
#define HWSZ    4096
#define NBATCH  64
#define SCOPE   27
#define NTILE_N 64
#define NTHREADS 256
#define NTILES_TOTAL (NBATCH * (HWSZ / NTILE_N))   // 4096

#define SPITCH_B 272                    // staging: 64 fp32 + 16B pad
#define XPITCH_B 272                    // fp16 buf: 128 fp16 + 16B pad
#define SMEM_STAGE 0
#define STAGE_B   (CCH * SPITCH_B)      // 34816 (128 k-rows)
#define SMEM_F16  STAGE_B
#define F16_B     (NTILE_N * XPITCH_B)  // 17408 (64 n-rows)
#define SMEM_DYN  (STAGE_B + F16_B)     // 52224

__device__ uint4 a_frag8[8 * 32];       // [class][lane], fp16 G frags

// ---------------------------------------------------------------------------
__device__ __forceinline__ uint32_t s2u(const void* p) {
    uint32_t a;
    asm("{ .reg .u64 t; cvta.to.shared.u64 t, %1; cvt.u32.u64 %0, t; }"
        : "=r"(a) : "l"(p));
    return a;
}
__device__ __forceinline__ uint32_t pack_f16x2(float lo, float hi) {
    uint32_t r;
    asm("cvt.rn.f16x2.f32 %0, %1, %2;" : "=r"(r) : "f"(hi), "f"(lo));
    return r;
}
__device__ __forceinline__ void cp_async16(uint32_t dst, const void* src) {
    asm volatile("cp.async.cg.shared.global [%0], [%1], 16;"
                 :: "r"(dst), "l"(src) : "memory");
}
__device__ __forceinline__ void cp_commit() {
    asm volatile("cp.async.commit_group;" ::: "memory");
}
__device__ __forceinline__ void cp_wait0() {
    asm volatile("cp.async.wait_group 0;" ::: "memory");
}
__device__ __forceinline__ void ldsm_x4(uint32_t& r0, uint32_t& r1,
                                        uint32_t& r2, uint32_t& r3, uint32_t a) {
    asm volatile("ldmatrix.sync.aligned.m8n8.x4.shared.b16 {%0,%1,%2,%3}, [%4];"
                 : "=r"(r0), "=r"(r1), "=r"(r2), "=r"(r3) : "r"(a));
}
__device__ __forceinline__ void mma16816(float* c, const uint4& a,
                                         uint32_t b0, uint32_t b1) {
    asm volatile(
        "mma.sync.aligned.m16n8k16.row.col.f32.f16.f16.f32 "
        "{%0,%1,%2,%3}, {%4,%5,%6,%7}, {%8,%9}, {%0,%1,%2,%3};"
        : "+f"(c[0]), "+f"(c[1]), "+f"(c[2]), "+f"(c[3])
        : "r"(a.x), "r"(a.y), "r"(a.z), "r"(a.w), "r"(b0), "r"(b1));
}

// ---------------------------------------------------------------------------
// Prep: compute g (validated R1), write the 8-class A-fragment table.
// ---------------------------------------------------------------------------
__global__ void prep_kernel(const float* __restrict__ filt) {
    __shared__ float tw_re[CCH], tw_im[CCH];
    __shared__ float inv_re[CCH], inv_im[CCH];
    __shared__ float ft[SCOPE];
    __shared__ float g_s[CCH];
    int t = threadIdx.x;   // 0..255
    if (t < SCOPE) ft[t] = filt[t];
    if (t < CCH) {
        float s, c;
        sincosf(6.283185307179586f * (float)t / 128.0f, &s, &c);
        tw_re[t] = c; tw_im[t] = s;
    }
    __syncthreads();
    if (t < CCH) {
        float fr = 1.0f, fi = 0.0f;
#pragma unroll
        for (int j = 0; j < SCOPE; j++) {
            int p = (115 + j) & 127;
            int idx = (t * p) & 127;
            fr -= ft[j] * tw_re[idx];
            fi += ft[j] * tw_im[idx];
        }
        float d = fr * fr + fi * fi;
        inv_re[t] = fr / d; inv_im[t] = -fi / d;
    }
    __syncthreads();
    if (t < CCH) {
        float acc = 0.0f;
        for (int f = 0; f < CCH; f++) {
            int idx = (f * t) & 127;
            acc += tw_re[idx] * inv_re[f] - tw_im[idx] * inv_im[f];
        }
        g_s[t] = acc * (1.0f / 128.0f);
    }
    __syncthreads();

    {
        int cls  = t >> 5;          // 0..7
        int lane = t & 31;
        int d0 = (16 * cls + (lane >> 2) - 2 * (lane & 3)) & 127;
        uint4 h;
        h.x = pack_f16x2(g_s[d0], g_s[(d0 - 1) & 127]);
        int d1 = (d0 + 8) & 127;
        h.y = pack_f16x2(g_s[d1], g_s[(d1 - 1) & 127]);
        int d2 = (d0 - 8) & 127;
        h.z = pack_f16x2(g_s[d2], g_s[(d2 - 1) & 127]);
        h.w = h.x;
        a_frag8[t] = h;
    }
}

// ---------------------------------------------------------------------------
// Persistent staged GEMM. Tile = 128 out-channels x 64 spatial cols.
// 8 warps: warp_m = wid&3 (32 rows), warp_n = wid>>2 (32 cols).
// ---------------------------------------------------------------------------
__global__ void __launch_bounds__(NTHREADS, 2)
gemm_mma(const float* __restrict__ x, float* __restrict__ y) {
    extern __shared__ char smc[];
    const int tid  = threadIdx.x;
    const int wid  = tid >> 5;
    const int lane = tid & 31;
    const int warp_m = wid & 3;
    const int warp_n = wid >> 2;

    // A fragments: 8 diagonal classes; index (mt - ks)&7 after folding warp_m.
    uint4 areg[8];
#pragma unroll
    for (int i = 0; i < 8; i++)
        areg[i] = a_frag8[(((warp_m * 2) + i) & 7) * 32 + lane];

    const uint32_t smb = s2u(smc);

    // convert-phase constants: thread -> (n-row n0, k-quarter kq)
    const int n0 = tid & 63;
    const int kq = tid >> 6;                 // 0..3
    const int rr = n0 & 31;
    const int nu = ((rr & 6) << 2) | ((rr >> 2) & 6) | (rr & 1);
    const int src_col = (n0 & ~31) + nu;     // permuted staging column

    // ldsm constants (fp16 buf rows = n, 64 rows, pitch 272)
    const uint32_t lm_off = ((lane & 7) + ((lane >> 4) << 3)) * XPITCH_B
                          + ((lane >> 3) & 1) * 16
                          + (uint32_t)warp_n * 32 * XPITCH_B;
    const uint32_t xh_base = smb + SMEM_F16 + lm_off;

    int tile = blockIdx.x;
    if (tile >= NTILES_TOTAL) return;
    const int stride = gridDim.x;

    // ---- prologue: stage tile0 ----
    {
        const float* xb = x + (size_t)(tile >> 6) * CCH * HWSZ
                            + (tile & 63) * NTILE_N;
#pragma unroll
        for (int i = 0; i < 8; i++) {
            int c = tid + NTHREADS * i;      // 0..2047 chunks
            int k = c >> 4, n4 = c & 15;
            cp_async16(smb + SMEM_STAGE + k * SPITCH_B + n4 * 16,
                       xb + (size_t)k * HWSZ + n4 * 4);
        }
        cp_commit();
    }

    for (; tile < NTILES_TOTAL; tile += stride) {
        const int nxt = tile + stride;
        const bool hn = nxt < NTILES_TOTAL;

        cp_wait0();
        __syncthreads();   // staging(tile) visible to all; fp16 buf free

        // ---- convert: staging fp32 [k][n] -> fp16 buf [n][k] (permuted) ----
        {
            const char* sk = smc + SMEM_STAGE + src_col * 4
                           + (size_t)(kq * 32) * SPITCH_B;
            char* dk = smc + SMEM_F16 + (uint32_t)n0 * XPITCH_B + kq * 64;
#pragma unroll
            for (int ch = 0; ch < 4; ch++) {
                float v[8];
#pragma unroll
                for (int ii = 0; ii < 8; ii++)
                    v[ii] = *reinterpret_cast<const float*>(
                        sk + (size_t)(ch * 8 + ii) * SPITCH_B);
                uint4 hq;
                hq.x = pack_f16x2(v[0], v[1]);
                hq.y = pack_f16x2(v[2], v[3]);
                hq.z = pack_f16x2(v[4], v[5]);
                hq.w = pack_f16x2(v[6], v[7]);
                *reinterpret_cast<uint4*>(dk + ch * 16) = hq;
            }
        }
        __syncthreads();   // fp16 buf ready; staging reads done

        // ---- stage next tile (covered by mma + epilogue) ----
        if (hn) {
            const float* xbn = x + (size_t)(nxt >> 6) * CCH * HWSZ
                                 + (nxt & 63) * NTILE_N;
#pragma unroll
            for (int i = 0; i < 8; i++) {
                int c = tid + NTHREADS * i;
                int k = c >> 4, n4 = c & 15;
                cp_async16(smb + SMEM_STAGE + k * SPITCH_B + n4 * 16,
                           xbn + (size_t)k * HWSZ + n4 * 4);
            }
        }
        cp_commit();

        // ---- mma: 2 mtiles x 4 ntiles, 8 ksteps ----
        float acc[2][4][4];
#pragma unroll
        for (int mt = 0; mt < 2; mt++)
#pragma unroll
            for (int nt = 0; nt < 4; nt++)
#pragma unroll
                for (int r = 0; r < 4; r++) acc[mt][nt][r] = 0.0f;

#pragma unroll
        for (int ks = 0; ks < 8; ks++) {
            const uint32_t kofs = (uint32_t)ks * 32;
#pragma unroll
            for (int p = 0; p < 2; p++) {
                uint32_t b0, b1, b2, b3;
                ldsm_x4(b0, b1, b2, b3, xh_base + p * (16 * XPITCH_B) + kofs);
#pragma unroll
                for (int mt = 0; mt < 2; mt++) {
                    const uint4& a = areg[(mt - ks) & 7];
                    mma16816(acc[mt][2 * p],     a, b0, b1);
                    mma16816(acc[mt][2 * p + 1], a, b2, b3);
                }
            }
        }

        // ---- epilogue: lane holds cols [8q,8q+8) of rows m0, m0+8 ----
        {
            float* yb = y + (size_t)(tile >> 6) * CCH * HWSZ
                          + (tile & 63) * NTILE_N;
            const int q = lane & 3;
#pragma unroll
            for (int mt = 0; mt < 2; mt++) {
                int m0 = warp_m * 32 + mt * 16 + (lane >> 2);
                float* yr0 = yb + (size_t)m0 * HWSZ + warp_n * 32 + 8 * q;
                float* yr8 = yr0 + (size_t)8 * HWSZ;
                *reinterpret_cast<float4*>(yr0) =
                    make_float4(acc[mt][0][0], acc[mt][0][1],
                                acc[mt][1][0], acc[mt][1][1]);
                *reinterpret_cast<float4*>(yr0 + 4) =
                    make_float4(acc[mt][2][0], acc[mt][2][1],
                                acc[mt][3][0], acc[mt][3][1]);
                *reinterpret_cast<float4*>(yr8) =
                    make_float4(acc[mt][0][2], acc[mt][0][3],
                                acc[mt][1][2], acc[mt][1][3]);
                *reinterpret_cast<float4*>(yr8 + 4) =
                    make_float4(acc[mt][2][2], acc[mt][2][3],
                                acc[mt][3][2], acc[mt][3][3]);
            }
        }
    }
}

// ---------------------------------------------------------------------------
extern "C" void kernel_launch(void* const* d_in, const int* in_sizes, int n_in,
                              void* d_out, int out_size) {
    const float* act  = (const float*)d_in[0];
    const float* filt = (const float*)d_in[1];
    if (n_in >= 2 && in_sizes[0] == SCOPE) {
        act  = (const float*)d_in[1];
        filt = (const float*)d_in[0];
    }
    float* out = (float*)d_out;

    prep_kernel<<<1, 256>>>(filt);

    int nsm = 148;
    cudaDeviceGetAttribute(&nsm, cudaDevAttrMultiProcessorCount, 0);
    int grid = 2 * nsm;
    if (grid > NTILES_TOTAL) grid = NTILES_TOTAL;

    cudaFuncSetAttribute(gemm_mma,
                         cudaFuncAttributeMaxDynamicSharedMemorySize, SMEM_DYN);
    gemm_mma<<<grid, NTHREADS, SMEM_DYN>>>(act, out);
}